// round 9
// baseline (speedup 1.0000x reference)
#include <cuda_runtime.h>
#include <cstddef>

// ---------------------------------------------------------------------------
// Problem constants (from reference)
// ---------------------------------------------------------------------------
constexpr int M0 = 123904, M1 = 11264, M2 = 1024;   // NUM_DST
constexpr int E0 = 1239040, E1 = 112640, E2 = 10240; // edges per layer
constexpr int F  = 128;                              // IN_FEATS == HID
constexpr int NCLS = 47;

// ---------------------------------------------------------------------------
// Scratch (device globals: no allocation allowed in kernel_launch).
// 16B-aligned: required for float4 stores and red.global.add.v4.f32.
// ---------------------------------------------------------------------------
__device__ __align__(16) float g_agg0[(size_t)M0 * F];
__device__ __align__(16) float g_deg0[M0];
__device__ __align__(16) float g_h0[(size_t)M0 * F];
__device__ __align__(16) float g_agg1[(size_t)M1 * F];
__device__ __align__(16) float g_deg1[M1];
__device__ __align__(16) float g_h1[(size_t)M1 * F];
__device__ __align__(16) float g_agg2[(size_t)M2 * F];
__device__ __align__(16) float g_deg2[M2];

// ---------------------------------------------------------------------------
// f32x2 packed-math helpers (Blackwell dual-rate fp32)
// ---------------------------------------------------------------------------
__device__ __forceinline__ unsigned long long pack2(float x, float y) {
    unsigned long long r;
    asm("mov.b64 %0, {%1, %2};" : "=l"(r) : "f"(x), "f"(y));
    return r;
}
__device__ __forceinline__ void unpack2(unsigned long long v, float& lo, float& hi) {
    asm("mov.b64 {%0, %1}, %2;" : "=f"(lo), "=f"(hi) : "l"(v));
}
__device__ __forceinline__ unsigned long long ffma2(unsigned long long a,
                                                    unsigned long long b,
                                                    unsigned long long c) {
    unsigned long long d;
    asm("fma.rn.f32x2 %0, %1, %2, %3;" : "=l"(d) : "l"(a), "l"(b), "l"(c));
    return d;
}

// ---------------------------------------------------------------------------
// Zero scratch (agg + deg) — grid-stride
// ---------------------------------------------------------------------------
__global__ void zero_kernel(float4* __restrict__ a, int n4,
                            float* __restrict__ d, int nd) {
    int idx = blockIdx.x * blockDim.x + threadIdx.x;
    int stride = gridDim.x * blockDim.x;
    float4 z = make_float4(0.f, 0.f, 0.f, 0.f);
    for (int i = idx; i < n4; i += stride) a[i] = z;
    for (int i = idx; i < nd; i += stride) d[i] = 0.f;
}

// ---------------------------------------------------------------------------
// Edge scatter: one warp per edge. Indices are INT32 (JAX demotes the
// requested int64 to int32 under default x64-disabled config).
// lane l gathers float4 at feature offset 4*l (streaming load, keep L2 for
// the atomic destination), then a single vector reduction red.global.add.v4.
// ---------------------------------------------------------------------------
__global__ void __launch_bounds__(256) scatter_kernel(
    const float* __restrict__ hsrc,
    const int* __restrict__ src,
    const int* __restrict__ dst,
    int E, float* __restrict__ agg, float* __restrict__ deg) {

    int warpId = (blockIdx.x * blockDim.x + threadIdx.x) >> 5;
    int lane   = threadIdx.x & 31;
    if (warpId >= E) return;

    int s = __ldg(src + warpId);
    int d = __ldg(dst + warpId);

    const float4* in = reinterpret_cast<const float4*>(hsrc + (size_t)s * F) + lane;
    float4 v = __ldcs(in);

    float* out = agg + (size_t)d * F + lane * 4;
    asm volatile("red.global.add.v4.f32 [%0], {%1, %2, %3, %4};"
                 :: "l"(out), "f"(v.x), "f"(v.y), "f"(v.z), "f"(v.w)
                 : "memory");
    if (lane == 0) atomicAdd(deg + d, 1.0f);
}

// ---------------------------------------------------------------------------
// Fused SAGE GEMM:  hout = act( hin[:M]@Wself + (agg/deg)@Wneigh + b )
// One combined K=256 GEMM processed as two K=128 chunks sharing accumulators.
// Block tile: 128 rows x 128 cols, 256 threads.
// smem: sAT[k][m] (transposed A chunk, 64KB) + sW[k][n] (64KB).
// Thread micro-tile: 16 rows (8 f32x2 m-pairs) x 4 cols -> 32 FFMA2 / k.
// ---------------------------------------------------------------------------
template <bool RELU>
__global__ void __launch_bounds__(256) gemm_fused(
    const float* __restrict__ hin, const float* __restrict__ agg,
    const float* __restrict__ deg, const float* __restrict__ Wself,
    const float* __restrict__ Wneigh, const float* __restrict__ bias,
    float* __restrict__ hout, int M) {

    extern __shared__ float smem[];
    float* sAT = smem;          // [128][128]  A^T chunk (k-major)
    float* sW  = smem + F * F;  // [128][128]  W chunk (k-major, same as global)

    const int t  = threadIdx.x;
    const int tx = t & 31;      // n lane (cols tx + 32*j)
    const int ty = t >> 5;      // 0..7    (m-pair groups)
    const int rowL = t >> 1;    // 0..127  fill row
    const int half = t & 1;     // k half for fill
    const int blockRow = blockIdx.x * F;

    unsigned long long acc[8][4];
#pragma unroll
    for (int i = 0; i < 8; i++)
#pragma unroll
        for (int j = 0; j < 4; j++) acc[i][j] = 0ull;

#pragma unroll
    for (int c = 0; c < 2; c++) {
        // ---- fill sW (layout identical to global [K][N]) ----
        const float4* W4 = reinterpret_cast<const float4*>(c == 0 ? Wself : Wneigh);
        float4* sW4 = reinterpret_cast<float4*>(sW);
#pragma unroll
        for (int it = 0; it < 16; it++) sW4[t + 256 * it] = W4[t + 256 * it];

        // ---- fill sAT (transposed). chunk0: hin rows; chunk1: agg*inv_deg ----
        {
            int gRow = blockRow + rowL;
            const float* srcRow =
                (c == 0 ? hin : agg) + (size_t)gRow * F + half * 64;
            float scale = 1.0f;
            if (c == 1) scale = 1.0f / fmaxf(deg[gRow], 1.0f);
#pragma unroll
            for (int it = 0; it < 16; it++) {
                float4 v = *reinterpret_cast<const float4*>(srcRow + it * 4);
                int k = half * 64 + it * 4;
                sAT[(k + 0) * F + rowL] = v.x * scale;
                sAT[(k + 1) * F + rowL] = v.y * scale;
                sAT[(k + 2) * F + rowL] = v.z * scale;
                sAT[(k + 3) * F + rowL] = v.w * scale;
            }
        }
        __syncthreads();

        // ---- main K loop (chunk of 128) ----
#pragma unroll 2
        for (int k = 0; k < F; k++) {
            const unsigned long long* aRow =
                reinterpret_cast<const unsigned long long*>(sAT + k * F);
            unsigned long long a2[8];
#pragma unroll
            for (int i = 0; i < 8; i++) a2[i] = aRow[ty * 8 + i];  // broadcast

            const float* wRow = sW + k * F + tx;
            unsigned long long w2[4];
#pragma unroll
            for (int j = 0; j < 4; j++) {
                float w = wRow[32 * j];
                w2[j] = pack2(w, w);
            }
#pragma unroll
            for (int i = 0; i < 8; i++)
#pragma unroll
                for (int j = 0; j < 4; j++)
                    acc[i][j] = ffma2(a2[i], w2[j], acc[i][j]);
        }
        __syncthreads();  // before chunk1 overwrites smem
    }

    // ---- epilogue: bias, activation, store ----
#pragma unroll
    for (int j = 0; j < 4; j++) {
        float bn = bias[tx + 32 * j];
#pragma unroll
        for (int i = 0; i < 8; i++) {
            float lo, hi;
            unpack2(acc[i][j], lo, hi);
            lo += bn; hi += bn;
            if (RELU) { lo = fmaxf(lo, 0.f); hi = fmaxf(hi, 0.f); }
            int gr = blockRow + 2 * (ty * 8 + i);
            hout[(size_t)gr * F + tx + 32 * j] = lo;
            hout[(size_t)(gr + 1) * F + tx + 32 * j] = hi;
        }
    }
}

// ---------------------------------------------------------------------------
// Layer 2: out[row, :47] = h1[row]@Ws2 + (agg2/deg2)[row]@Wn2 + b2  (no relu)
// One block per dst row; trivial FLOPs.
// ---------------------------------------------------------------------------
__global__ void __launch_bounds__(128) layer2_kernel(
    const float* __restrict__ h1, const float* __restrict__ agg,
    const float* __restrict__ deg, const float* __restrict__ Ws,
    const float* __restrict__ Wn, const float* __restrict__ bias,
    float* __restrict__ out) {

    __shared__ float sIn[2 * F];
    int row = blockIdx.x;
    int t = threadIdx.x;
    float inv = 1.0f / fmaxf(deg[row], 1.0f);
    sIn[t]       = h1[(size_t)row * F + t];
    sIn[F + t]   = agg[(size_t)row * F + t] * inv;
    __syncthreads();

    if (t < NCLS) {
        float acc = bias[t];
#pragma unroll 4
        for (int k = 0; k < F; k++) acc += sIn[k] * Ws[k * NCLS + t];
#pragma unroll 4
        for (int k = 0; k < F; k++) acc += sIn[F + k] * Wn[k * NCLS + t];
        out[row * NCLS + t] = acc;
    }
}

// ---------------------------------------------------------------------------
// Launch
// ---------------------------------------------------------------------------
extern "C" void kernel_launch(void* const* d_in, const int* in_sizes, int n_in,
                              void* d_out, int out_size) {
    (void)in_sizes; (void)n_in; (void)out_size;

    const float* x   = (const float*)d_in[0];
    const float* Ws0 = (const float*)d_in[1];
    const float* Wn0 = (const float*)d_in[2];
    const float* b0  = (const float*)d_in[3];
    const float* Ws1 = (const float*)d_in[4];
    const float* Wn1 = (const float*)d_in[5];
    const float* b1  = (const float*)d_in[6];
    const float* Ws2 = (const float*)d_in[7];
    const float* Wn2 = (const float*)d_in[8];
    const float* b2  = (const float*)d_in[9];
    const int* src0 = (const int*)d_in[10];
    const int* dst0 = (const int*)d_in[11];
    const int* src1 = (const int*)d_in[12];
    const int* dst1 = (const int*)d_in[13];
    const int* src2 = (const int*)d_in[14];
    const int* dst2 = (const int*)d_in[15];
    float* out = (float*)d_out;

    float *agg0, *deg0, *h0, *agg1, *deg1, *h1, *agg2, *deg2;
    cudaGetSymbolAddress((void**)&agg0, g_agg0);
    cudaGetSymbolAddress((void**)&deg0, g_deg0);
    cudaGetSymbolAddress((void**)&h0,   g_h0);
    cudaGetSymbolAddress((void**)&agg1, g_agg1);
    cudaGetSymbolAddress((void**)&deg1, g_deg1);
    cudaGetSymbolAddress((void**)&h1,   g_h1);
    cudaGetSymbolAddress((void**)&agg2, g_agg2);
    cudaGetSymbolAddress((void**)&deg2, g_deg2);

    const int smemBytes = 2 * F * F * (int)sizeof(float);  // 128 KB
    cudaFuncSetAttribute(gemm_fused<true>,
                         cudaFuncAttributeMaxDynamicSharedMemorySize, smemBytes);

    // ---- layer 0 ----
    zero_kernel<<<1024, 256>>>((float4*)agg0, M0 * F / 4, deg0, M0);
    scatter_kernel<<<(E0 * 32 + 255) / 256, 256>>>(x, src0, dst0, E0, agg0, deg0);
    gemm_fused<true><<<M0 / F, 256, smemBytes>>>(x, agg0, deg0, Ws0, Wn0, b0, h0, M0);

    // ---- layer 1 ----
    zero_kernel<<<512, 256>>>((float4*)agg1, M1 * F / 4, deg1, M1);
    scatter_kernel<<<(E1 * 32 + 255) / 256, 256>>>(h0, src1, dst1, E1, agg1, deg1);
    gemm_fused<true><<<M1 / F, 256, smemBytes>>>(h0, agg1, deg1, Ws1, Wn1, b1, h1, M1);

    // ---- layer 2 ----
    zero_kernel<<<128, 256>>>((float4*)agg2, M2 * F / 4, deg2, M2);
    scatter_kernel<<<(E2 * 32 + 255) / 256, 256>>>(h1, src2, dst2, E2, agg2, deg2);
    layer2_kernel<<<M2, 128>>>(h1, agg2, deg2, Ws2, Wn2, b2, out);
}

// round 10
// speedup vs baseline: 1.0002x; 1.0002x over previous
#include <cuda_runtime.h>
#include <cstddef>

// ---------------------------------------------------------------------------
// Problem constants (from reference)
// ---------------------------------------------------------------------------
constexpr int M0 = 123904, M1 = 11264, M2 = 1024;   // NUM_DST
constexpr int E0 = 1239040, E1 = 112640, E2 = 10240; // edges per layer
constexpr int F  = 128;                              // IN_FEATS == HID
constexpr int NCLS = 47;

// ---------------------------------------------------------------------------
// Scratch (device globals: no allocation allowed in kernel_launch).
// 16B-aligned: required for float4 stores and red.global.add.v4.f32.
// ---------------------------------------------------------------------------
__device__ __align__(16) float g_agg0[(size_t)M0 * F];
__device__ __align__(16) float g_deg0[M0];
__device__ __align__(16) float g_h0[(size_t)M0 * F];
__device__ __align__(16) float g_agg1[(size_t)M1 * F];
__device__ __align__(16) float g_deg1[M1];
__device__ __align__(16) float g_h1[(size_t)M1 * F];
__device__ __align__(16) float g_agg2[(size_t)M2 * F];
__device__ __align__(16) float g_deg2[M2];

// ---------------------------------------------------------------------------
// f32x2 packed-math helpers (Blackwell dual-rate fp32)
// ---------------------------------------------------------------------------
__device__ __forceinline__ unsigned long long pack2(float x, float y) {
    unsigned long long r;
    asm("mov.b64 %0, {%1, %2};" : "=l"(r) : "f"(x), "f"(y));
    return r;
}
__device__ __forceinline__ void unpack2(unsigned long long v, float& lo, float& hi) {
    asm("mov.b64 {%0, %1}, %2;" : "=f"(lo), "=f"(hi) : "l"(v));
}
__device__ __forceinline__ unsigned long long ffma2(unsigned long long a,
                                                    unsigned long long b,
                                                    unsigned long long c) {
    unsigned long long d;
    asm("fma.rn.f32x2 %0, %1, %2, %3;" : "=l"(d) : "l"(a), "l"(b), "l"(c));
    return d;
}

// ---------------------------------------------------------------------------
// Zero scratch (agg + deg) — grid-stride
// ---------------------------------------------------------------------------
__global__ void zero_kernel(float4* __restrict__ a, int n4,
                            float* __restrict__ d, int nd) {
    int idx = blockIdx.x * blockDim.x + threadIdx.x;
    int stride = gridDim.x * blockDim.x;
    float4 z = make_float4(0.f, 0.f, 0.f, 0.f);
    for (int i = idx; i < n4; i += stride) a[i] = z;
    for (int i = idx; i < nd; i += stride) d[i] = 0.f;
}

// ---------------------------------------------------------------------------
// Edge scatter: one warp per edge. Indices are INT32 (JAX demotes the
// requested int64 to int32 under default x64-disabled config).
// lane l gathers float4 at feature offset 4*l (streaming load, keep L2 for
// the atomic destination), then a single vector reduction red.global.add.v4.
// ---------------------------------------------------------------------------
__global__ void __launch_bounds__(256) scatter_kernel(
    const float* __restrict__ hsrc,
    const int* __restrict__ src,
    const int* __restrict__ dst,
    int E, float* __restrict__ agg, float* __restrict__ deg) {

    int warpId = (blockIdx.x * blockDim.x + threadIdx.x) >> 5;
    int lane   = threadIdx.x & 31;
    if (warpId >= E) return;

    int s = __ldg(src + warpId);
    int d = __ldg(dst + warpId);

    const float4* in = reinterpret_cast<const float4*>(hsrc + (size_t)s * F) + lane;
    float4 v = __ldcs(in);

    float* out = agg + (size_t)d * F + lane * 4;
    asm volatile("red.global.add.v4.f32 [%0], {%1, %2, %3, %4};"
                 :: "l"(out), "f"(v.x), "f"(v.y), "f"(v.z), "f"(v.w)
                 : "memory");
    if (lane == 0) atomicAdd(deg + d, 1.0f);
}

// ---------------------------------------------------------------------------
// Fused SAGE GEMM:  hout = act( hin[:M]@Wself + (agg/deg)@Wneigh + b )
// One combined K=256 GEMM processed as two K=128 chunks sharing accumulators.
// Block tile: 128 rows x 128 cols, 256 threads.
// smem: sAT[k][m] (transposed A chunk, 64KB) + sW[k][n] (64KB).
// Thread micro-tile: 16 rows (8 f32x2 m-pairs) x 4 cols -> 32 FFMA2 / k.
// ---------------------------------------------------------------------------
template <bool RELU>
__global__ void __launch_bounds__(256) gemm_fused(
    const float* __restrict__ hin, const float* __restrict__ agg,
    const float* __restrict__ deg, const float* __restrict__ Wself,
    const float* __restrict__ Wneigh, const float* __restrict__ bias,
    float* __restrict__ hout, int M) {

    extern __shared__ float smem[];
    float* sAT = smem;          // [128][128]  A^T chunk (k-major)
    float* sW  = smem + F * F;  // [128][128]  W chunk (k-major, same as global)

    const int t  = threadIdx.x;
    const int tx = t & 31;      // n lane (cols tx + 32*j)
    const int ty = t >> 5;      // 0..7    (m-pair groups)
    const int rowL = t >> 1;    // 0..127  fill row
    const int half = t & 1;     // k half for fill
    const int blockRow = blockIdx.x * F;

    unsigned long long acc[8][4];
#pragma unroll
    for (int i = 0; i < 8; i++)
#pragma unroll
        for (int j = 0; j < 4; j++) acc[i][j] = 0ull;

#pragma unroll
    for (int c = 0; c < 2; c++) {
        // ---- fill sW (layout identical to global [K][N]) ----
        const float4* W4 = reinterpret_cast<const float4*>(c == 0 ? Wself : Wneigh);
        float4* sW4 = reinterpret_cast<float4*>(sW);
#pragma unroll
        for (int it = 0; it < 16; it++) sW4[t + 256 * it] = W4[t + 256 * it];

        // ---- fill sAT (transposed). chunk0: hin rows; chunk1: agg*inv_deg ----
        {
            int gRow = blockRow + rowL;
            const float* srcRow =
                (c == 0 ? hin : agg) + (size_t)gRow * F + half * 64;
            float scale = 1.0f;
            if (c == 1) scale = 1.0f / fmaxf(deg[gRow], 1.0f);
#pragma unroll
            for (int it = 0; it < 16; it++) {
                float4 v = *reinterpret_cast<const float4*>(srcRow + it * 4);
                int k = half * 64 + it * 4;
                sAT[(k + 0) * F + rowL] = v.x * scale;
                sAT[(k + 1) * F + rowL] = v.y * scale;
                sAT[(k + 2) * F + rowL] = v.z * scale;
                sAT[(k + 3) * F + rowL] = v.w * scale;
            }
        }
        __syncthreads();

        // ---- main K loop (chunk of 128) ----
#pragma unroll 2
        for (int k = 0; k < F; k++) {
            const unsigned long long* aRow =
                reinterpret_cast<const unsigned long long*>(sAT + k * F);
            unsigned long long a2[8];
#pragma unroll
            for (int i = 0; i < 8; i++) a2[i] = aRow[ty * 8 + i];  // broadcast

            const float* wRow = sW + k * F + tx;
            unsigned long long w2[4];
#pragma unroll
            for (int j = 0; j < 4; j++) {
                float w = wRow[32 * j];
                w2[j] = pack2(w, w);
            }
#pragma unroll
            for (int i = 0; i < 8; i++)
#pragma unroll
                for (int j = 0; j < 4; j++)
                    acc[i][j] = ffma2(a2[i], w2[j], acc[i][j]);
        }
        __syncthreads();  // before chunk1 overwrites smem
    }

    // ---- epilogue: bias, activation, store ----
#pragma unroll
    for (int j = 0; j < 4; j++) {
        float bn = bias[tx + 32 * j];
#pragma unroll
        for (int i = 0; i < 8; i++) {
            float lo, hi;
            unpack2(acc[i][j], lo, hi);
            lo += bn; hi += bn;
            if (RELU) { lo = fmaxf(lo, 0.f); hi = fmaxf(hi, 0.f); }
            int gr = blockRow + 2 * (ty * 8 + i);
            hout[(size_t)gr * F + tx + 32 * j] = lo;
            hout[(size_t)(gr + 1) * F + tx + 32 * j] = hi;
        }
    }
}

// ---------------------------------------------------------------------------
// Layer 2: out[row, :47] = h1[row]@Ws2 + (agg2/deg2)[row]@Wn2 + b2  (no relu)
// One block per dst row; trivial FLOPs.
// ---------------------------------------------------------------------------
__global__ void __launch_bounds__(128) layer2_kernel(
    const float* __restrict__ h1, const float* __restrict__ agg,
    const float* __restrict__ deg, const float* __restrict__ Ws,
    const float* __restrict__ Wn, const float* __restrict__ bias,
    float* __restrict__ out) {

    __shared__ float sIn[2 * F];
    int row = blockIdx.x;
    int t = threadIdx.x;
    float inv = 1.0f / fmaxf(deg[row], 1.0f);
    sIn[t]       = h1[(size_t)row * F + t];
    sIn[F + t]   = agg[(size_t)row * F + t] * inv;
    __syncthreads();

    if (t < NCLS) {
        float acc = bias[t];
#pragma unroll 4
        for (int k = 0; k < F; k++) acc += sIn[k] * Ws[k * NCLS + t];
#pragma unroll 4
        for (int k = 0; k < F; k++) acc += sIn[F + k] * Wn[k * NCLS + t];
        out[row * NCLS + t] = acc;
    }
}

// ---------------------------------------------------------------------------
// Launch
// ---------------------------------------------------------------------------
extern "C" void kernel_launch(void* const* d_in, const int* in_sizes, int n_in,
                              void* d_out, int out_size) {
    (void)in_sizes; (void)n_in; (void)out_size;

    const float* x   = (const float*)d_in[0];
    const float* Ws0 = (const float*)d_in[1];
    const float* Wn0 = (const float*)d_in[2];
    const float* b0  = (const float*)d_in[3];
    const float* Ws1 = (const float*)d_in[4];
    const float* Wn1 = (const float*)d_in[5];
    const float* b1  = (const float*)d_in[6];
    const float* Ws2 = (const float*)d_in[7];
    const float* Wn2 = (const float*)d_in[8];
    const float* b2  = (const float*)d_in[9];
    const int* src0 = (const int*)d_in[10];
    const int* dst0 = (const int*)d_in[11];
    const int* src1 = (const int*)d_in[12];
    const int* dst1 = (const int*)d_in[13];
    const int* src2 = (const int*)d_in[14];
    const int* dst2 = (const int*)d_in[15];
    float* out = (float*)d_out;

    float *agg0, *deg0, *h0, *agg1, *deg1, *h1, *agg2, *deg2;
    cudaGetSymbolAddress((void**)&agg0, g_agg0);
    cudaGetSymbolAddress((void**)&deg0, g_deg0);
    cudaGetSymbolAddress((void**)&h0,   g_h0);
    cudaGetSymbolAddress((void**)&agg1, g_agg1);
    cudaGetSymbolAddress((void**)&deg1, g_deg1);
    cudaGetSymbolAddress((void**)&h1,   g_h1);
    cudaGetSymbolAddress((void**)&agg2, g_agg2);
    cudaGetSymbolAddress((void**)&deg2, g_deg2);

    const int smemBytes = 2 * F * F * (int)sizeof(float);  // 128 KB
    cudaFuncSetAttribute(gemm_fused<true>,
                         cudaFuncAttributeMaxDynamicSharedMemorySize, smemBytes);

    // ---- layer 0 ----
    zero_kernel<<<1024, 256>>>((float4*)agg0, M0 * F / 4, deg0, M0);
    scatter_kernel<<<(E0 * 32 + 255) / 256, 256>>>(x, src0, dst0, E0, agg0, deg0);
    gemm_fused<true><<<M0 / F, 256, smemBytes>>>(x, agg0, deg0, Ws0, Wn0, b0, h0, M0);

    // ---- layer 1 ----
    zero_kernel<<<512, 256>>>((float4*)agg1, M1 * F / 4, deg1, M1);
    scatter_kernel<<<(E1 * 32 + 255) / 256, 256>>>(h0, src1, dst1, E1, agg1, deg1);
    gemm_fused<true><<<M1 / F, 256, smemBytes>>>(h0, agg1, deg1, Ws1, Wn1, b1, h1, M1);

    // ---- layer 2 ----
    zero_kernel<<<128, 256>>>((float4*)agg2, M2 * F / 4, deg2, M2);
    scatter_kernel<<<(E2 * 32 + 255) / 256, 256>>>(h1, src2, dst2, E2, agg2, deg2);
    layer2_kernel<<<M2, 128>>>(h1, agg2, deg2, Ws2, Wn2, b2, out);
}

// round 11
// speedup vs baseline: 1.0694x; 1.0692x over previous
#include <cuda_runtime.h>
#include <cstddef>

// ---------------------------------------------------------------------------
// Problem constants
// ---------------------------------------------------------------------------
constexpr int M0 = 123904, M1 = 11264, M2 = 1024;    // NUM_DST
constexpr int E0 = 1239040, E1 = 112640, E2 = 10240; // edges per layer
constexpr int F  = 128;                              // IN_FEATS == HID
constexpr int NCLS = 47;

// ---------------------------------------------------------------------------
// Scratch (device globals). All layer M / E values divide the block sizes
// exactly (M = NB*256, E = EB*256), so no ragged-edge handling is needed.
// ---------------------------------------------------------------------------
__device__ __align__(16) float g_agg0[(size_t)M0 * F];
__device__ __align__(16) float g_h0[(size_t)M0 * F];
__device__ __align__(16) float g_agg1[(size_t)M1 * F];
__device__ __align__(16) float g_h1[(size_t)M1 * F];
__device__ __align__(16) float g_agg2[(size_t)M2 * F];
__device__ __align__(16) int   g_cnt[M0];
__device__ __align__(16) int   g_fill[M0];
__device__ __align__(16) int   g_base[M0];
__device__ __align__(16) int   g_bsums[512];
__device__ __align__(16) int   g_csr[E0];

// ---------------------------------------------------------------------------
// f32x2 packed-math helpers (Blackwell dual-rate fp32)
// ---------------------------------------------------------------------------
__device__ __forceinline__ unsigned long long pack2(float x, float y) {
    unsigned long long r;
    asm("mov.b64 %0, {%1, %2};" : "=l"(r) : "f"(x), "f"(y));
    return r;
}
__device__ __forceinline__ void unpack2(unsigned long long v, float& lo, float& hi) {
    asm("mov.b64 {%0, %1}, %2;" : "=f"(lo), "=f"(hi) : "l"(v));
}
__device__ __forceinline__ unsigned long long ffma2(unsigned long long a,
                                                    unsigned long long b,
                                                    unsigned long long c) {
    unsigned long long d;
    asm("fma.rn.f32x2 %0, %1, %2, %3;" : "=l"(d) : "l"(a), "l"(b), "l"(c));
    return d;
}

// ---------------------------------------------------------------------------
// CSR-build kernels
// ---------------------------------------------------------------------------
__global__ void zero_ints(int* __restrict__ a, int na, int* __restrict__ b, int nb) {
    int idx = blockIdx.x * blockDim.x + threadIdx.x;
    int stride = gridDim.x * blockDim.x;
    for (int i = idx; i < na; i += stride) a[i] = 0;
    for (int i = idx; i < nb; i += stride) b[i] = 0;
}

__global__ void hist_kernel(const int* __restrict__ dst, int E, int* __restrict__ cnt) {
    int e = blockIdx.x * blockDim.x + threadIdx.x;
    if (e < E) atomicAdd(cnt + __ldg(dst + e), 1);
}

// Block-wise exclusive scan of cnt -> base (partial), block totals -> bsums.
__global__ void scanA(const int* __restrict__ cnt, int M,
                      int* __restrict__ base, int* __restrict__ bsums) {
    __shared__ int s[256];
    int tid = threadIdx.x;
    int i = blockIdx.x * 256 + tid;
    int v = (i < M) ? cnt[i] : 0;
    s[tid] = v;
    __syncthreads();
#pragma unroll
    for (int off = 1; off < 256; off <<= 1) {
        int t = (tid >= off) ? s[tid - off] : 0;
        __syncthreads();
        s[tid] += t;
        __syncthreads();
    }
    if (i < M) base[i] = s[tid] - v;            // exclusive
    if (tid == 255) bsums[blockIdx.x] = s[255]; // block total
}

// Single-block exclusive scan of block totals (nb <= 512).
__global__ void scanB(int* __restrict__ bsums, int nb) {
    __shared__ int s[512];
    int tid = threadIdx.x;
    int v = (tid < nb) ? bsums[tid] : 0;
    s[tid] = v;
    __syncthreads();
#pragma unroll
    for (int off = 1; off < 512; off <<= 1) {
        int t = (tid >= off) ? s[tid - off] : 0;
        __syncthreads();
        s[tid] += t;
        __syncthreads();
    }
    if (tid < nb) bsums[tid] = s[tid] - v;      // exclusive
}

__global__ void scanC(int* __restrict__ base, int M, const int* __restrict__ bsums) {
    int i = blockIdx.x * 256 + threadIdx.x;
    if (i < M) base[i] += bsums[blockIdx.x];
}

__global__ void permute_kernel(const int* __restrict__ src, const int* __restrict__ dst,
                               int E, const int* __restrict__ base,
                               int* __restrict__ fill, int* __restrict__ csr) {
    int e = blockIdx.x * blockDim.x + threadIdx.x;
    if (e >= E) return;
    int d = __ldg(dst + e);
    int p = atomicAdd(fill + d, 1);
    csr[__ldg(base + d) + p] = __ldg(src + e);
}

// ---------------------------------------------------------------------------
// Gather-reduce aggregation: one warp per dst row, lane = float4 slice.
// Src indices broadcast via shfl; unroll-4 inner loop for MLP.
// Writes mean (agg/deg) directly -> no fp atomics, no zero pass, no deg array.
// ---------------------------------------------------------------------------
__global__ void __launch_bounds__(256) aggregate_kernel(
    const float* __restrict__ hsrc, const int* __restrict__ csr,
    const int* __restrict__ base, const int* __restrict__ cnt,
    float* __restrict__ agg, int M) {

    int warp = (blockIdx.x * blockDim.x + threadIdx.x) >> 5;
    int lane = threadIdx.x & 31;
    if (warp >= M) return;  // warp-uniform

    int n  = __ldg(cnt + warp);
    int st = __ldg(base + warp);

    float4 acc = make_float4(0.f, 0.f, 0.f, 0.f);
    int i = 0;
    while (i < n) {
        int chunk = min(n - i, 32);
        int myIdx = (lane < chunk) ? __ldg(csr + st + i + lane) : 0;
        int j = 0;
        for (; j + 4 <= chunk; j += 4) {
            int s0 = __shfl_sync(0xFFFFFFFFu, myIdx, j);
            int s1 = __shfl_sync(0xFFFFFFFFu, myIdx, j + 1);
            int s2 = __shfl_sync(0xFFFFFFFFu, myIdx, j + 2);
            int s3 = __shfl_sync(0xFFFFFFFFu, myIdx, j + 3);
            float4 v0 = __ldcs(reinterpret_cast<const float4*>(hsrc + (size_t)s0 * F) + lane);
            float4 v1 = __ldcs(reinterpret_cast<const float4*>(hsrc + (size_t)s1 * F) + lane);
            float4 v2 = __ldcs(reinterpret_cast<const float4*>(hsrc + (size_t)s2 * F) + lane);
            float4 v3 = __ldcs(reinterpret_cast<const float4*>(hsrc + (size_t)s3 * F) + lane);
            acc.x += (v0.x + v1.x) + (v2.x + v3.x);
            acc.y += (v0.y + v1.y) + (v2.y + v3.y);
            acc.z += (v0.z + v1.z) + (v2.z + v3.z);
            acc.w += (v0.w + v1.w) + (v2.w + v3.w);
        }
        for (; j < chunk; j++) {
            int s = __shfl_sync(0xFFFFFFFFu, myIdx, j);
            float4 v = __ldcs(reinterpret_cast<const float4*>(hsrc + (size_t)s * F) + lane);
            acc.x += v.x; acc.y += v.y; acc.z += v.z; acc.w += v.w;
        }
        i += chunk;
    }
    float sc = 1.0f / fmaxf((float)n, 1.0f);
    float4 r = make_float4(acc.x * sc, acc.y * sc, acc.z * sc, acc.w * sc);
    *(reinterpret_cast<float4*>(agg + (size_t)warp * F) + lane) = r;
}

// ---------------------------------------------------------------------------
// Fused SAGE GEMM:  hout = act( hin[:M]@Wself + agg@Wneigh + b )
// (agg is pre-normalized.) Combined K=256 as two K=128 chunks, 128x128 tile,
// 256 threads, sAT transposed in smem, 16x4 micro-tile of f32x2 pairs.
// ---------------------------------------------------------------------------
template <bool RELU>
__global__ void __launch_bounds__(256) gemm_fused(
    const float* __restrict__ hin, const float* __restrict__ agg,
    const float* __restrict__ Wself, const float* __restrict__ Wneigh,
    const float* __restrict__ bias, float* __restrict__ hout, int M) {

    extern __shared__ float smem[];
    float* sAT = smem;          // [128][128]  A^T chunk (k-major)
    float* sW  = smem + F * F;  // [128][128]  W chunk

    const int t  = threadIdx.x;
    const int tx = t & 31;
    const int ty = t >> 5;
    const int rowL = t >> 1;
    const int half = t & 1;
    const int blockRow = blockIdx.x * F;

    unsigned long long acc[8][4];
#pragma unroll
    for (int i = 0; i < 8; i++)
#pragma unroll
        for (int j = 0; j < 4; j++) acc[i][j] = 0ull;

#pragma unroll
    for (int c = 0; c < 2; c++) {
        const float4* W4 = reinterpret_cast<const float4*>(c == 0 ? Wself : Wneigh);
        float4* sW4 = reinterpret_cast<float4*>(sW);
#pragma unroll
        for (int it = 0; it < 16; it++) sW4[t + 256 * it] = W4[t + 256 * it];

        {
            int gRow = blockRow + rowL;
            const float* srcRow = (c == 0 ? hin : agg) + (size_t)gRow * F + half * 64;
#pragma unroll
            for (int it = 0; it < 16; it++) {
                float4 v = *reinterpret_cast<const float4*>(srcRow + it * 4);
                int k = half * 64 + it * 4;
                sAT[(k + 0) * F + rowL] = v.x;
                sAT[(k + 1) * F + rowL] = v.y;
                sAT[(k + 2) * F + rowL] = v.z;
                sAT[(k + 3) * F + rowL] = v.w;
            }
        }
        __syncthreads();

#pragma unroll 2
        for (int k = 0; k < F; k++) {
            const unsigned long long* aRow =
                reinterpret_cast<const unsigned long long*>(sAT + k * F);
            unsigned long long a2[8];
#pragma unroll
            for (int i = 0; i < 8; i++) a2[i] = aRow[ty * 8 + i];

            const float* wRow = sW + k * F + tx;
            unsigned long long w2[4];
#pragma unroll
            for (int j = 0; j < 4; j++) {
                float w = wRow[32 * j];
                w2[j] = pack2(w, w);
            }
#pragma unroll
            for (int i = 0; i < 8; i++)
#pragma unroll
                for (int j = 0; j < 4; j++)
                    acc[i][j] = ffma2(a2[i], w2[j], acc[i][j]);
        }
        __syncthreads();
    }

#pragma unroll
    for (int j = 0; j < 4; j++) {
        float bn = bias[tx + 32 * j];
#pragma unroll
        for (int i = 0; i < 8; i++) {
            float lo, hi;
            unpack2(acc[i][j], lo, hi);
            lo += bn; hi += bn;
            if (RELU) { lo = fmaxf(lo, 0.f); hi = fmaxf(hi, 0.f); }
            int gr = blockRow + 2 * (ty * 8 + i);
            hout[(size_t)gr * F + tx + 32 * j] = lo;
            hout[(size_t)(gr + 1) * F + tx + 32 * j] = hi;
        }
    }
}

// ---------------------------------------------------------------------------
// Layer 2: out[row,:47] = h1[row]@Ws2 + agg2[row]@Wn2 + b2 (agg pre-normed)
// ---------------------------------------------------------------------------
__global__ void __launch_bounds__(128) layer2_kernel(
    const float* __restrict__ h1, const float* __restrict__ agg,
    const float* __restrict__ Ws, const float* __restrict__ Wn,
    const float* __restrict__ bias, float* __restrict__ out) {

    __shared__ float sIn[2 * F];
    int row = blockIdx.x;
    int t = threadIdx.x;
    sIn[t]     = h1[(size_t)row * F + t];
    sIn[F + t] = agg[(size_t)row * F + t];
    __syncthreads();

    if (t < NCLS) {
        float acc = bias[t];
#pragma unroll 4
        for (int k = 0; k < F; k++) acc += sIn[k] * Ws[k * NCLS + t];
#pragma unroll 4
        for (int k = 0; k < F; k++) acc += sIn[F + k] * Wn[k * NCLS + t];
        out[row * NCLS + t] = acc;
    }
}

// ---------------------------------------------------------------------------
// Launch
// ---------------------------------------------------------------------------
static inline void run_layer_agg(const float* h, const int* src, const int* dst,
                                 int E, int M, float* agg,
                                 int* cnt, int* fill, int* base, int* bsums, int* csr) {
    int NB = M / 256;   // exact for all layers
    int EB = E / 256;   // exact for all layers
    zero_ints<<<256, 256>>>(cnt, M, fill, M);
    hist_kernel<<<EB, 256>>>(dst, E, cnt);
    scanA<<<NB, 256>>>(cnt, M, base, bsums);
    scanB<<<1, 512>>>(bsums, NB);
    scanC<<<NB, 256>>>(base, M, bsums);
    permute_kernel<<<EB, 256>>>(src, dst, E, base, fill, csr);
    aggregate_kernel<<<M / 8, 256>>>(h, csr, base, cnt, agg, M);
}

extern "C" void kernel_launch(void* const* d_in, const int* in_sizes, int n_in,
                              void* d_out, int out_size) {
    (void)in_sizes; (void)n_in; (void)out_size;

    const float* x   = (const float*)d_in[0];
    const float* Ws0 = (const float*)d_in[1];
    const float* Wn0 = (const float*)d_in[2];
    const float* b0  = (const float*)d_in[3];
    const float* Ws1 = (const float*)d_in[4];
    const float* Wn1 = (const float*)d_in[5];
    const float* b1  = (const float*)d_in[6];
    const float* Ws2 = (const float*)d_in[7];
    const float* Wn2 = (const float*)d_in[8];
    const float* b2  = (const float*)d_in[9];
    const int* src0 = (const int*)d_in[10];
    const int* dst0 = (const int*)d_in[11];
    const int* src1 = (const int*)d_in[12];
    const int* dst1 = (const int*)d_in[13];
    const int* src2 = (const int*)d_in[14];
    const int* dst2 = (const int*)d_in[15];
    float* out = (float*)d_out;

    float *agg0, *h0, *agg1, *h1, *agg2;
    int *cnt, *fill, *base, *bsums, *csr;
    cudaGetSymbolAddress((void**)&agg0, g_agg0);
    cudaGetSymbolAddress((void**)&h0,   g_h0);
    cudaGetSymbolAddress((void**)&agg1, g_agg1);
    cudaGetSymbolAddress((void**)&h1,   g_h1);
    cudaGetSymbolAddress((void**)&agg2, g_agg2);
    cudaGetSymbolAddress((void**)&cnt,  g_cnt);
    cudaGetSymbolAddress((void**)&fill, g_fill);
    cudaGetSymbolAddress((void**)&base, g_base);
    cudaGetSymbolAddress((void**)&bsums, g_bsums);
    cudaGetSymbolAddress((void**)&csr,  g_csr);

    const int smemBytes = 2 * F * F * (int)sizeof(float);  // 128 KB
    cudaFuncSetAttribute(gemm_fused<true>,
                         cudaFuncAttributeMaxDynamicSharedMemorySize, smemBytes);

    // ---- layer 0 ----
    run_layer_agg(x, src0, dst0, E0, M0, agg0, cnt, fill, base, bsums, csr);
    gemm_fused<true><<<M0 / F, 256, smemBytes>>>(x, agg0, Ws0, Wn0, b0, h0, M0);

    // ---- layer 1 ----
    run_layer_agg(h0, src1, dst1, E1, M1, agg1, cnt, fill, base, bsums, csr);
    gemm_fused<true><<<M1 / F, 256, smemBytes>>>(h0, agg1, Ws1, Wn1, b1, h1, M1);

    // ---- layer 2 ----
    run_layer_agg(h1, src2, dst2, E2, M2, agg2, cnt, fill, base, bsums, csr);
    layer2_kernel<<<M2, 128>>>(h1, agg2, Ws2, Wn2, b2, out);
}